// round 9
// baseline (speedup 1.0000x reference)
#include <cuda_runtime.h>

#define NODES  8448
#define NB     10
#define ITERS  5
#define TPB    1024
#define NPTMAX 9             // ceil(8448/1024); threads 0..255 do 9, rest do 8
#define NBATCH 1024
#define RPC    4             // batch rows per CTA (packed as float4)
#define NGROUPS (NBATCH / RPC)   // 256
#define NQG    (NODES / 8)   // 1056 quarter-warp node groups

#define SMEM_BYTES (NODES * 16)  // float4 tanh table = 135168 B

// Global scratch (static __device__ arrays; no allocation).
__device__ unsigned int g_pk[5][NODES];       // u16 neighbor ids, 2-per-u32, slot-SoA
__device__ float4       g_wllr[NGROUPS][NODES];
__device__ float4       g_P[NGROUPS][NODES];  // vm_{t-1}

// ---------------------------------------------------------------------------
// Prep: for each aligned group of 8 nodes (one LDS quarter-warp phase), permute
// each node's 10 neighbor indices among the 10 gather slots so that, per slot,
// the 8 lanes' bank-groups (idx % 8) are as distinct as possible. The check
// product is commutative, so any per-node permutation is exact.
//
// Parallelization: 8 threads per group (one per lane-node). Each thread loads
// its own 10 indices (MLP=10). The greedy is serialized over the 8 lanes via
// 8 steps; the nibble-packed occupancy counters are passed between lanes with
// __shfl_sync(width=8). A warp covers 4 groups in lockstep -> 264 warps total.
__global__ void prep_sched_kernel(const int* __restrict__ check_idx)
{
    const int t   = blockIdx.x * blockDim.x + threadIdx.x;
    const int grp = t >> 3;
    const int ln  = t & 7;
    if (grp >= NQG) return;
    const int n = grp * 8 + ln;

    unsigned idxv[10];
    #pragma unroll
    for (int j = 0; j < 10; j++)
        idxv[j] = (unsigned)check_idx[n * NB + j];

    unsigned cnt[10];                 // per-slot, 8 nibble bank-group counts
    #pragma unroll
    for (int s = 0; s < 10; s++) cnt[s] = 0u;

    unsigned perm[10];

    #pragma unroll
    for (int step = 0; step < 8; step++) {
        if (ln == step) {
            unsigned used = 0;        // bitmask of assigned slots
            #pragma unroll
            for (int j = 0; j < 10; j++) {
                const unsigned v  = idxv[j];
                const unsigned sh = (v & 7u) * 4u;   // nibble shift for bank-group
                int best = 0, bestc = 1 << 30;
                #pragma unroll
                for (int s = 0; s < 10; s++) {
                    const int c = (int)((cnt[s] >> sh) & 0xFu);
                    const bool free_slot = ((used >> s) & 1u) == 0u;
                    if (free_slot && c < bestc) { bestc = c; best = s; }
                }
                used |= 1u << best;
                #pragma unroll
                for (int s = 0; s < 10; s++)
                    if (s == best) { cnt[s] += 1u << sh; perm[s] = v; }
            }
        }
        // broadcast the updated counters from lane 'step' of this 8-lane group
        #pragma unroll
        for (int s = 0; s < 10; s++)
            cnt[s] = __shfl_sync(0xFFFFFFFFu, cnt[s], step, 8);
    }

    // pack slot pairs (2j, 2j+1) into u32, slot-SoA layout
    #pragma unroll
    for (int j = 0; j < 5; j++)
        g_pk[j][n] = (perm[2 * j] & 0xFFFFu) | (perm[2 * j + 1] << 16);
}

// ---------------------------------------------------------------------------
__global__ __launch_bounds__(TPB, 1)
void ldpc4_kernel(const float* __restrict__ input_llr,
                  const float* __restrict__ w_ch,
                  const float* __restrict__ w_res,   // (2, NODES)
                  float*       __restrict__ out)
{
    extern __shared__ float4 st[];                   // tanh values, 4 rows packed
    const int tid  = threadIdx.x;
    const int g    = blockIdx.x;
    const int row0 = g * RPC;
    const float* llr0 = input_llr + (size_t)row0 * NODES;

    float4 cur[NPTMAX];   // current var_messages for this thread's nodes (4 rows)

    // Prologue: weighted LLR -> registers + global scratch.
    #pragma unroll
    for (int i = 0; i < NPTMAX; i++) {
        const int n = tid + i * TPB;
        if (n < NODES) {
            const float wc = w_ch[n];
            float4 wl;
            wl.x = llr0[n]             * wc;
            wl.y = llr0[NODES + n]     * wc;
            wl.z = llr0[2 * NODES + n] * wc;
            wl.w = llr0[3 * NODES + n] * wc;
            g_wllr[g][n] = wl;
            cur[i] = wl;
        }
    }

    for (int it = 0; it < ITERS; it++) {
        // Phase A: publish t = tanh(clip(0.5 * vm)) for all 4 rows (one STS.128).
        #pragma unroll
        for (int i = 0; i < NPTMAX; i++) {
            const int n = tid + i * TPB;
            if (n < NODES) {
                const float4 v = cur[i];
                float4 t;
                t.x = tanhf(fminf(9.9f, fmaxf(-9.9f, 0.5f * v.x)));
                t.y = tanhf(fminf(9.9f, fmaxf(-9.9f, 0.5f * v.y)));
                t.z = tanhf(fminf(9.9f, fmaxf(-9.9f, 0.5f * v.z)));
                t.w = tanhf(fminf(9.9f, fmaxf(-9.9f, 0.5f * v.w)));
                st[n] = t;
            }
        }
        __syncthreads();

        // Phase B: gather 10 scheduled neighbors (LDS.128 serves 4 rows),
        // product, 2*atanh, residual, update.
        #pragma unroll 2
        for (int i = 0; i < NPTMAX; i++) {
            const int n = tid + i * TPB;
            if (n < NODES) {
                const unsigned pk0 = g_pk[0][n], pk1 = g_pk[1][n];
                const unsigned pk2 = g_pk[2][n], pk3 = g_pk[3][n];
                const unsigned pk4 = g_pk[4][n];

                // prefetch iteration-state (L2 latency overlaps LDS work)
                float4 pr = make_float4(0.f, 0.f, 0.f, 0.f);
                if (it > 0) pr = g_P[g][n];
                const float4 wl = g_wllr[g][n];
                const float  w0 = w_res[n];
                const float  w1 = w_res[NODES + n];

                float4 p0 = st[pk0 & 0xFFFFu];
                float4 p1 = st[pk0 >> 16];
                {
                    const float4 a = st[pk1 & 0xFFFFu];
                    const float4 b = st[pk1 >> 16];
                    p0.x *= a.x; p0.y *= a.y; p0.z *= a.z; p0.w *= a.w;
                    p1.x *= b.x; p1.y *= b.y; p1.z *= b.z; p1.w *= b.w;
                }
                {
                    const float4 a = st[pk2 & 0xFFFFu];
                    const float4 b = st[pk2 >> 16];
                    p0.x *= a.x; p0.y *= a.y; p0.z *= a.z; p0.w *= a.w;
                    p1.x *= b.x; p1.y *= b.y; p1.z *= b.z; p1.w *= b.w;
                }
                {
                    const float4 a = st[pk3 & 0xFFFFu];
                    const float4 b = st[pk3 >> 16];
                    p0.x *= a.x; p0.y *= a.y; p0.z *= a.z; p0.w *= a.w;
                    p1.x *= b.x; p1.y *= b.y; p1.z *= b.z; p1.w *= b.w;
                }
                {
                    const float4 a = st[pk4 & 0xFFFFu];
                    const float4 b = st[pk4 >> 16];
                    p0.x *= a.x; p0.y *= a.y; p0.z *= a.z; p0.w *= a.w;
                    p1.x *= b.x; p1.y *= b.y; p1.z *= b.z; p1.w *= b.w;
                }
                float4 p;
                p.x = p0.x * p1.x;  p.y = p0.y * p1.y;
                p.z = p0.z * p1.z;  p.w = p0.w * p1.w;

                p.x = fminf(0.999999f, fmaxf(-0.999999f, p.x));
                p.y = fminf(0.999999f, fmaxf(-0.999999f, p.y));
                p.z = fminf(0.999999f, fmaxf(-0.999999f, p.z));
                p.w = fminf(0.999999f, fmaxf(-0.999999f, p.w));
                float4 cm;
                cm.x = logf((1.0f + p.x) / (1.0f - p.x));   // 2*atanh(p)
                cm.y = logf((1.0f + p.y) / (1.0f - p.y));
                cm.z = logf((1.0f + p.z) / (1.0f - p.z));
                cm.w = logf((1.0f + p.w) / (1.0f - p.w));

                const float4 c = cur[i];
                if (it < ITERS - 1) g_P[g][n] = c;     // dead on last iteration

                float4 nv;
                nv.x = wl.x + cm.x + w0 * c.x + w1 * pr.x;
                nv.y = wl.y + cm.y + w0 * c.y + w1 * pr.y;
                nv.z = wl.z + cm.z + w0 * c.z + w1 * pr.z;
                nv.w = wl.w + cm.w + w0 * c.w + w1 * pr.w;
                cur[i] = nv;
            }
        }
        __syncthreads();   // protect st before next iteration's Phase A
    }

    // Epilogue: soft_bits = sigmoid(vm + input_llr), 4 coalesced row streams.
    #pragma unroll
    for (int i = 0; i < NPTMAX; i++) {
        const int n = tid + i * TPB;
        if (n < NODES) {
            const float4 c = cur[i];
            float* o = out + (size_t)row0 * NODES;
            const float zx = c.x + llr0[n];
            const float zy = c.y + llr0[NODES + n];
            const float zz = c.z + llr0[2 * NODES + n];
            const float zw = c.w + llr0[3 * NODES + n];
            o[n]             = 1.0f / (1.0f + expf(-zx));
            o[NODES + n]     = 1.0f / (1.0f + expf(-zy));
            o[2 * NODES + n] = 1.0f / (1.0f + expf(-zz));
            o[3 * NODES + n] = 1.0f / (1.0f + expf(-zw));
        }
    }
}

// ---------------------------------------------------------------------------
extern "C" void kernel_launch(void* const* d_in, const int* in_sizes, int n_in,
                              void* d_out, int out_size)
{
    const float* input_llr = (const float*)d_in[0];
    const float* w_ch      = (const float*)d_in[1];
    const float* w_res     = (const float*)d_in[2];
    const int*   check_idx = (const int*)d_in[3];
    // d_in[4] (var_index_tensor) is unused by the reference computation.
    float* out = (float*)d_out;

    prep_sched_kernel<<<(NQG * 8 + 255) / 256, 256>>>(check_idx);

    cudaFuncSetAttribute(ldpc4_kernel,
                         cudaFuncAttributeMaxDynamicSharedMemorySize, SMEM_BYTES);
    ldpc4_kernel<<<NGROUPS, TPB, SMEM_BYTES>>>(input_llr, w_ch, w_res, out);
}

// round 10
// speedup vs baseline: 1.1555x; 1.1555x over previous
#include <cuda_runtime.h>

#define NODES  8448
#define NB     10
#define ITERS  5
#define TPB    1024
#define NPTMAX 9             // ceil(8448/1024); threads 0..255 do 9, rest do 8
#define NBATCH 1024
#define RPC    4             // batch rows per CTA (packed as float4)
#define NGROUPS (NBATCH / RPC)   // 256
#define NQG    (NODES / 8)   // 1056 quarter-warp node groups

#define SMEM_BYTES (NODES * 16)  // float4 tanh table = 135168 B

// Global scratch (static __device__ arrays; no allocation).
__device__ unsigned int g_pk[5][NODES];       // u16 neighbor ids, 2-per-u32, slot-SoA
__device__ float4       g_wllr[NGROUPS][NODES];
__device__ float4       g_P[NGROUPS][NODES];  // vm_{t-1}

// ---------------------------------------------------------------------------
// Prep: for each aligned group of 8 nodes (one LDS quarter-warp phase), permute
// each node's 10 neighbor indices among the 10 gather slots so that, per slot,
// the 8 lanes' bank-groups (idx % 8) are as distinct as possible. The check
// product is commutative, so any per-node permutation is exact.
//
// ONE WARP PER GROUP. Threads 0..9 each own one slot's nibble-packed bank-group
// counter. The 80 greedy steps stay serial, but each argmin-over-slots is a
// single REDUX.SYNC.MIN (key = count<<8 | slot, so ties pick the lowest slot —
// bit-identical schedule to the R7 sequential greedy). 1056 warps run
// concurrently (~7/SM), so the serial chain is paid once in parallel.
__global__ void prep_sched_kernel(const int* __restrict__ check_idx)
{
    const int warp = (blockIdx.x * blockDim.x + threadIdx.x) >> 5;
    const int lane = threadIdx.x & 31;
    if (warp >= NQG) return;

    const int base = warp * 80;          // 8 nodes * 10 indices
    // Load all 80 group indices into 3 registers across the warp.
    const unsigned v0 = (unsigned)check_idx[base + lane];
    const unsigned v1 = (unsigned)check_idx[base + 32 + lane];
    const unsigned v2 = (lane < 16) ? (unsigned)check_idx[base + 64 + lane] : 0u;

    const bool is_slot = (lane < 10);
    unsigned cnt = 0u;                   // my slot's 8 nibble bank-group counts

    #pragma unroll
    for (int ln = 0; ln < 8; ln++) {
        unsigned taken = 0u;             // my slot already used for this node?
        unsigned perm  = 0u;             // value assigned to my slot

        #pragma unroll
        for (int j = 0; j < 10; j++) {
            const int flat = ln * 10 + j;          // compile-time constant
            unsigned v;
            if      (flat < 32) v = __shfl_sync(0xFFFFFFFFu, v0, flat);
            else if (flat < 64) v = __shfl_sync(0xFFFFFFFFu, v1, flat - 32);
            else                v = __shfl_sync(0xFFFFFFFFu, v2, flat - 64);

            const unsigned sh = (v & 7u) * 4u;     // nibble shift for bank-group
            const unsigned c  = (cnt >> sh) & 0xFu;
            const unsigned key = (is_slot && !taken) ? ((c << 8) | (unsigned)lane)
                                                     : 0xFFFFu;
            const unsigned best = __reduce_min_sync(0xFFFFFFFFu, key) & 0xFFu;
            if ((unsigned)lane == best) {
                taken = 1u;
                cnt  += 1u << sh;
                perm  = v;
            }
        }
        // Threads 0..9 hold this node's permuted indices by slot; pack pairs.
        const unsigned plo = __shfl_sync(0xFFFFFFFFu, perm, (lane << 1), 32);
        const unsigned phi = __shfl_sync(0xFFFFFFFFu, perm, (lane << 1) + 1, 32);
        if (lane < 5)
            g_pk[lane][warp * 8 + ln] = (plo & 0xFFFFu) | (phi << 16);
    }
}

// ---------------------------------------------------------------------------
__global__ __launch_bounds__(TPB, 1)
void ldpc4_kernel(const float* __restrict__ input_llr,
                  const float* __restrict__ w_ch,
                  const float* __restrict__ w_res,   // (2, NODES)
                  float*       __restrict__ out)
{
    extern __shared__ float4 st[];                   // tanh values, 4 rows packed
    const int tid  = threadIdx.x;
    const int g    = blockIdx.x;
    const int row0 = g * RPC;
    const float* llr0 = input_llr + (size_t)row0 * NODES;

    float4 cur[NPTMAX];   // current var_messages for this thread's nodes (4 rows)

    // Prologue: weighted LLR -> registers + global scratch.
    #pragma unroll
    for (int i = 0; i < NPTMAX; i++) {
        const int n = tid + i * TPB;
        if (n < NODES) {
            const float wc = w_ch[n];
            float4 wl;
            wl.x = llr0[n]             * wc;
            wl.y = llr0[NODES + n]     * wc;
            wl.z = llr0[2 * NODES + n] * wc;
            wl.w = llr0[3 * NODES + n] * wc;
            g_wllr[g][n] = wl;
            cur[i] = wl;
        }
    }

    for (int it = 0; it < ITERS; it++) {
        // Phase A: publish t = tanh(clip(0.5 * vm)) for all 4 rows (one STS.128).
        #pragma unroll
        for (int i = 0; i < NPTMAX; i++) {
            const int n = tid + i * TPB;
            if (n < NODES) {
                const float4 v = cur[i];
                float4 t;
                t.x = tanhf(fminf(9.9f, fmaxf(-9.9f, 0.5f * v.x)));
                t.y = tanhf(fminf(9.9f, fmaxf(-9.9f, 0.5f * v.y)));
                t.z = tanhf(fminf(9.9f, fmaxf(-9.9f, 0.5f * v.z)));
                t.w = tanhf(fminf(9.9f, fmaxf(-9.9f, 0.5f * v.w)));
                st[n] = t;
            }
        }
        __syncthreads();

        // Phase B: gather 10 scheduled neighbors (LDS.128 serves 4 rows),
        // product, 2*atanh, residual, update.
        #pragma unroll 2
        for (int i = 0; i < NPTMAX; i++) {
            const int n = tid + i * TPB;
            if (n < NODES) {
                const unsigned pk0 = g_pk[0][n], pk1 = g_pk[1][n];
                const unsigned pk2 = g_pk[2][n], pk3 = g_pk[3][n];
                const unsigned pk4 = g_pk[4][n];

                // prefetch iteration-state (L2 latency overlaps LDS work)
                float4 pr = make_float4(0.f, 0.f, 0.f, 0.f);
                if (it > 0) pr = g_P[g][n];
                const float4 wl = g_wllr[g][n];
                const float  w0 = w_res[n];
                const float  w1 = w_res[NODES + n];

                float4 p0 = st[pk0 & 0xFFFFu];
                float4 p1 = st[pk0 >> 16];
                {
                    const float4 a = st[pk1 & 0xFFFFu];
                    const float4 b = st[pk1 >> 16];
                    p0.x *= a.x; p0.y *= a.y; p0.z *= a.z; p0.w *= a.w;
                    p1.x *= b.x; p1.y *= b.y; p1.z *= b.z; p1.w *= b.w;
                }
                {
                    const float4 a = st[pk2 & 0xFFFFu];
                    const float4 b = st[pk2 >> 16];
                    p0.x *= a.x; p0.y *= a.y; p0.z *= a.z; p0.w *= a.w;
                    p1.x *= b.x; p1.y *= b.y; p1.z *= b.z; p1.w *= b.w;
                }
                {
                    const float4 a = st[pk3 & 0xFFFFu];
                    const float4 b = st[pk3 >> 16];
                    p0.x *= a.x; p0.y *= a.y; p0.z *= a.z; p0.w *= a.w;
                    p1.x *= b.x; p1.y *= b.y; p1.z *= b.z; p1.w *= b.w;
                }
                {
                    const float4 a = st[pk4 & 0xFFFFu];
                    const float4 b = st[pk4 >> 16];
                    p0.x *= a.x; p0.y *= a.y; p0.z *= a.z; p0.w *= a.w;
                    p1.x *= b.x; p1.y *= b.y; p1.z *= b.z; p1.w *= b.w;
                }
                float4 p;
                p.x = p0.x * p1.x;  p.y = p0.y * p1.y;
                p.z = p0.z * p1.z;  p.w = p0.w * p1.w;

                p.x = fminf(0.999999f, fmaxf(-0.999999f, p.x));
                p.y = fminf(0.999999f, fmaxf(-0.999999f, p.y));
                p.z = fminf(0.999999f, fmaxf(-0.999999f, p.z));
                p.w = fminf(0.999999f, fmaxf(-0.999999f, p.w));
                float4 cm;
                cm.x = logf((1.0f + p.x) / (1.0f - p.x));   // 2*atanh(p)
                cm.y = logf((1.0f + p.y) / (1.0f - p.y));
                cm.z = logf((1.0f + p.z) / (1.0f - p.z));
                cm.w = logf((1.0f + p.w) / (1.0f - p.w));

                const float4 c = cur[i];
                if (it < ITERS - 1) g_P[g][n] = c;     // dead on last iteration

                float4 nv;
                nv.x = wl.x + cm.x + w0 * c.x + w1 * pr.x;
                nv.y = wl.y + cm.y + w0 * c.y + w1 * pr.y;
                nv.z = wl.z + cm.z + w0 * c.z + w1 * pr.z;
                nv.w = wl.w + cm.w + w0 * c.w + w1 * pr.w;
                cur[i] = nv;
            }
        }
        __syncthreads();   // protect st before next iteration's Phase A
    }

    // Epilogue: soft_bits = sigmoid(vm + input_llr), 4 coalesced row streams.
    #pragma unroll
    for (int i = 0; i < NPTMAX; i++) {
        const int n = tid + i * TPB;
        if (n < NODES) {
            const float4 c = cur[i];
            float* o = out + (size_t)row0 * NODES;
            const float zx = c.x + llr0[n];
            const float zy = c.y + llr0[NODES + n];
            const float zz = c.z + llr0[2 * NODES + n];
            const float zw = c.w + llr0[3 * NODES + n];
            o[n]             = 1.0f / (1.0f + expf(-zx));
            o[NODES + n]     = 1.0f / (1.0f + expf(-zy));
            o[2 * NODES + n] = 1.0f / (1.0f + expf(-zz));
            o[3 * NODES + n] = 1.0f / (1.0f + expf(-zw));
        }
    }
}

// ---------------------------------------------------------------------------
extern "C" void kernel_launch(void* const* d_in, const int* in_sizes, int n_in,
                              void* d_out, int out_size)
{
    const float* input_llr = (const float*)d_in[0];
    const float* w_ch      = (const float*)d_in[1];
    const float* w_res     = (const float*)d_in[2];
    const int*   check_idx = (const int*)d_in[3];
    // d_in[4] (var_index_tensor) is unused by the reference computation.
    float* out = (float*)d_out;

    // one warp per group: NQG * 32 threads
    prep_sched_kernel<<<(NQG * 32 + 255) / 256, 256>>>(check_idx);

    cudaFuncSetAttribute(ldpc4_kernel,
                         cudaFuncAttributeMaxDynamicSharedMemorySize, SMEM_BYTES);
    ldpc4_kernel<<<NGROUPS, TPB, SMEM_BYTES>>>(input_llr, w_ch, w_res, out);
}